// round 15
// baseline (speedup 1.0000x reference)
#include <cuda_runtime.h>
#include <cuda_fp16.h>

#define N_KKA 288
#define N_P   512
#define N_LOC 196
#define N_BL  784   // 4 * 196
#define TILE  56    // bl per kernel-A CTA (784 = 56*14); 4 blanes * 14 idx

#define CACHED_I 5           // i < 5 slices cached in smem (80 of 288 kka)
#define SRED_ST  514         // h2 stride (16 warps * 32 + 2 pad)

typedef unsigned long long ull;

// 231 MB fp16 scratch, chunk-interleaved: half index =
//   bl*(288*512) + kka*512 + j*256 + bc*8 + dd   (d = j*8+dd, j=0..1)
__device__ __half2 g_po[(size_t)N_BL * N_KKA * 256];

__device__ __forceinline__ ull ffma2(ull a, ull b, ull c) {
    ull d;
    asm("fma.rn.f32x2 %0, %1, %2, %3;" : "=l"(d) : "l"(a), "l"(b), "l"(c));
    return d;
}
__device__ __forceinline__ ull pack2(float lo, float hi) {
    ull d;
    asm("mov.b64 %0, {%1, %2};" : "=l"(d) : "f"(lo), "f"(hi));
    return d;
}
__device__ __forceinline__ void unpack2(float& lo, float& hi, ull v) {
    asm("mov.b64 {%0, %1}, %2;" : "=f"(lo), "=f"(hi) : "l"(v));
}
// pack f32x2 accumulator -> half2 bits (lo -> low half, hi -> high half)
__device__ __forceinline__ unsigned cvt_h2(ull v) {
    float lo, hi;
    unpack2(lo, hi, v);
    unsigned r;
    asm("cvt.rn.f16x2.f32 %0, %1, %2;" : "=r"(r) : "f"(hi), "f"(lo));
    return r;
}
__device__ __forceinline__ void cp_async16(unsigned saddr, const void* gptr) {
    asm volatile("cp.async.cg.shared.global [%0], [%1], 16;"
                 :: "r"(saddr), "l"(gptr));
}

// ---------------------------------------------------------------------------
// Kernel A (v3): pose_out[bl, kka, p] = sum_c W[kka, p, c] * x[bl, kka, c]
// 256 threads: thread = (chunk = t&63, blane = t>>6). chunk -> (j = chunk>>5,
// bc = chunk&31), p-range p0 = bc*16 + j*8 .. p0+7 (8 contiguous dd).
// W block (8p x 8c) loaded into a constant-indexed register array (NO pointer
// cast -> no local-memory spill, the round-14 bug), packed into 32 f32x2 regs.
// x duplicated in smem as (x,x) ull -> LDS.64 broadcast.
// Per blc: 32 FFMA2 + 4 cvt + 1 STG.128 (warp = 512B contiguous).
// ---------------------------------------------------------------------------
__global__ void __launch_bounds__(256) pose_out_kernel(
        const float* __restrict__ pose, const float* __restrict__ W) {
    const int kka  = blockIdx.x;
    const int tile = blockIdx.y;
    __shared__ ull xsmD[8][TILE];   // (x,x) duplicated, [c][blc]
    const int t = threadIdx.x;
    const int chunk = t & 63, blane = t >> 6;
    const int j = chunk >> 5, bc = chunk & 31;
    const int p0 = bc * 16 + j * 8;

    // ---- load this thread's W block: 8p x 8c, constant-indexed regs ----
    const float4* Wf4 = (const float4*)(W + (size_t)kka * (N_P * 8)) + p0 * 2;
    float wreg[64];   // wreg[dp*8 + c] = W[p0+dp][c]; all indices constant
#pragma unroll
    for (int i = 0; i < 16; i++) {
        const float4 w4 = Wf4[i];
        wreg[4 * i + 0] = w4.x;
        wreg[4 * i + 1] = w4.y;
        wreg[4 * i + 2] = w4.z;
        wreg[4 * i + 3] = w4.w;
    }
    ull wd[8][4];   // [c][e] = (W[p0+2e][c], W[p0+2e+1][c])
#pragma unroll
    for (int c = 0; c < 8; c++)
#pragma unroll
        for (int e = 0; e < 4; e++)
            wd[c][e] = pack2(wreg[(2 * e) * 8 + c], wreg[(2 * e + 1) * 8 + c]);

    // ---- fill x (duplicated) ----
    const int a = kka & 31, kk = kka >> 5;
    const int ky = kk / 3, kx = kk % 3;
#pragma unroll
    for (int idx = t; idx < TILE * 8; idx += 256) {
        const int blc = idx >> 3, c = idx & 7;
        const int bl = tile * TILE + blc;
        const int b = bl / N_LOC, l = bl % N_LOC;
        const int oh = l / 14, ow = l % 14;
        const int ih = oh + ky - 1, iw = ow + kx - 1;
        float val = 0.f;
        if ((unsigned)ih < 14u && (unsigned)iw < 14u)
            val = pose[((b * 256 + a * 8 + c) * 14 + ih) * 14 + iw];
        xsmD[c][blc] = pack2(val, val);
    }
    __syncthreads();

    // ---- main loop: 14 blc per thread (blc = blane + idx*4) ----
    uint4* dst0 = (uint4*)g_po +
                  ((size_t)(tile * TILE + blane) * (N_KKA * 64) + kka * 64 + chunk);
#pragma unroll 2
    for (int idx = 0; idx < 14; idx++) {
        const int blc = blane + idx * 4;
        ull acc[4] = {0ull, 0ull, 0ull, 0ull};
#pragma unroll
        for (int c = 0; c < 8; c++) {
            const ull x2 = xsmD[c][blc];   // LDS.64 broadcast
            acc[0] = ffma2(wd[c][0], x2, acc[0]);
            acc[1] = ffma2(wd[c][1], x2, acc[1]);
            acc[2] = ffma2(wd[c][2], x2, acc[2]);
            acc[3] = ffma2(wd[c][3], x2, acc[3]);
        }
        uint4 o;
        o.x = cvt_h2(acc[0]);
        o.y = cvt_h2(acc[1]);
        o.z = cvt_h2(acc[2]);
        o.w = cvt_h2(acc[3]);
        dst0[(size_t)(idx * 4) * (N_KKA * 64)] = o;   // STG.128
    }
}

// ---------------------------------------------------------------------------
// Kernel B helpers (unchanged from round 12)
// ---------------------------------------------------------------------------
__device__ __forceinline__ float softmax_c(float lg) {
    float es;
    {
        const float x = fmaf(lg, 1.44269504f, 16.0f);
        asm("ex2.approx.f32 %0, %1;" : "=f"(es) : "f"(x));
    }
    const unsigned ei = __float2uint_rn(es);
    unsigned si;
    asm("redux.sync.add.u32 %0, %1, 0xffffffff;" : "=r"(si) : "r"(ei));
    return __fdividef(es, __uint2float_rn(si));
}

#define SM_SRED  81920
#define SM_VSM   98368
#define SM_TOTAL 99520

__device__ __forceinline__ float reduce_squash16(
        char* smem_raw, const __half2 s2[8], int t, int wid, int lane) {
    __half2* sred  = (__half2*)(smem_raw + SM_SRED);
    __half*  sredh = (__half*)(smem_raw + SM_SRED);
    __half*  vsm_h = (__half*)(smem_raw + SM_VSM);

#pragma unroll
    for (int j = 0; j < 8; j++)
        sred[j * SRED_ST + wid * 32 + lane] = s2[j];
    __syncthreads();

    const int bc = t >> 4, d = t & 15, j = d >> 1, par = d & 1;
    float stot = 0.f;
#pragma unroll
    for (int w = 0; w < 16; w++)
        stot += __half2float(sredh[2 * (j * SRED_ST + w * 32 + bc) + par]);

    float magsq = stot * stot;
#pragma unroll
    for (int off = 8; off; off >>= 1)
        magsq += __shfl_xor_sync(0xffffffffu, magsq, off);
    const float vv = stot * magsq / ((1.f + magsq) * sqrtf(magsq));
    vsm_h[bc * 18 + d] = __float2half_rn(vv);
    __syncthreads();
    return vv;
}

// ---------------------------------------------------------------------------
// Kernel B: unchanged from round 12 (512 thr, 2 CTAs/SM, vsum trick).
// ---------------------------------------------------------------------------
extern __shared__ char smem_raw[];

__global__ void __launch_bounds__(512, 2) routing_kernel(float* __restrict__ out) {
    float4* cache4 = (float4*)smem_raw;
    __half* vsm_h  = (__half*)(smem_raw + SM_VSM);

    const int bl = blockIdx.x;
    const int b = bl / N_LOC, l = bl % N_LOC;
    const int t = threadIdx.x;
    const int wid = t >> 5, lane = t & 31;

    const float4* po4 = (const float4*)(g_po + (size_t)bl * (N_KKA * 256));

    __half2 vsum2[8];
    float vout = 0.f;

    // ---------------- pass 0 ----------------
    {
        __half2 s2[8];
#pragma unroll
        for (int j = 0; j < 8; j++) s2[j] = __float2half2_rn(0.f);
        const __half2 c2 = __float2half2_rn(0.03125f);

        const unsigned cbase = (unsigned)__cvta_generic_to_shared(cache4);
#pragma unroll
        for (int i = 0; i < CACHED_I; i++) {
            const int kka = i * 16 + wid;
            const unsigned dst = cbase + (unsigned)((kka * 64 + lane) * 16);
            cp_async16(dst,       po4 + kka * 64 + lane);
            cp_async16(dst + 512, po4 + kka * 64 + 32 + lane);
        }
        asm volatile("cp.async.commit_group;");

        float4 q0 = po4[(CACHED_I * 16 + wid) * 64 + lane];
        float4 q1 = po4[(CACHED_I * 16 + wid) * 64 + 32 + lane];
#pragma unroll
        for (int i = CACHED_I; i < 18; i++) {
            float4 n0 = q0, n1 = q1;
            if (i < 17) {
                const int kka = (i + 1) * 16 + wid;
                n0 = po4[kka * 64 + lane];
                n1 = po4[kka * 64 + 32 + lane];
            }
            const __half2* h0 = (const __half2*)&q0;
            const __half2* h1 = (const __half2*)&q1;
#pragma unroll
            for (int j = 0; j < 4; j++) {
                s2[j]     = __hfma2(c2, h0[j], s2[j]);
                s2[4 + j] = __hfma2(c2, h1[j], s2[4 + j]);
            }
            q0 = n0; q1 = n1;
        }

        asm volatile("cp.async.wait_group 0;" ::: "memory");
#pragma unroll
        for (int i = 0; i < CACHED_I; i++) {
            const int slot = (i * 16 + wid) * 64;
            const float4 c0 = cache4[slot + lane];
            const float4 c1 = cache4[slot + 32 + lane];
            const __half2* h0 = (const __half2*)&c0;
            const __half2* h1 = (const __half2*)&c1;
#pragma unroll
            for (int j = 0; j < 4; j++) {
                s2[j]     = __hfma2(c2, h0[j], s2[j]);
                s2[4 + j] = __hfma2(c2, h1[j], s2[4 + j]);
            }
        }

        reduce_squash16(smem_raw, s2, t, wid, lane);
#pragma unroll
        for (int j = 0; j < 8; j++)
            vsum2[j] = *(const __half2*)&vsm_h[lane * 18 + 2 * j];
    }

    // ---------------- passes 1 and 2 ----------------
#pragma unroll 1
    for (int pass = 1; pass < 3; pass++) {
        __half2 s2[8];
#pragma unroll
        for (int j = 0; j < 8; j++) s2[j] = __float2half2_rn(0.f);

        float4 q0 = cache4[wid * 64 + lane];
        float4 q1 = cache4[wid * 64 + 32 + lane];
#pragma unroll
        for (int i = 0; i < 18; i++) {
            float4 n0 = q0, n1 = q1;
            if (i < 17) {
                const int ii = i + 1;
                if (ii < CACHED_I) {
                    const int slot = (ii * 16 + wid) * 64;
                    n0 = cache4[slot + lane];
                    n1 = cache4[slot + 32 + lane];
                } else {
                    const int kka = ii * 16 + wid;
                    n0 = po4[kka * 64 + lane];
                    n1 = po4[kka * 64 + 32 + lane];
                }
            }
            __half2 r2[8];
            {
                const __half2* h0 = (const __half2*)&q0;
                const __half2* h1 = (const __half2*)&q1;
#pragma unroll
                for (int j = 0; j < 4; j++) { r2[j] = h0[j]; r2[4 + j] = h1[j]; }
            }
            __half2 acc0 = __hmul2(vsum2[0], r2[0]);
            acc0 = __hfma2(vsum2[1], r2[1], acc0);
            acc0 = __hfma2(vsum2[2], r2[2], acc0);
            acc0 = __hfma2(vsum2[3], r2[3], acc0);
            __half2 acc1 = __hmul2(vsum2[4], r2[4]);
            acc1 = __hfma2(vsum2[5], r2[5], acc1);
            acc1 = __hfma2(vsum2[6], r2[6], acc1);
            acc1 = __hfma2(vsum2[7], r2[7], acc1);
            const float2 df = __half22float2(__hadd2(acc0, acc1));
            const float lg = df.x + df.y;
            const __half2 c2 = __half2half2(__float2half_rn(softmax_c(lg)));
#pragma unroll
            for (int j = 0; j < 8; j++) s2[j] = __hfma2(c2, r2[j], s2[j]);
            q0 = n0; q1 = n1;
        }

        const float vv = reduce_squash16(smem_raw, s2, t, wid, lane);
        if (pass == 2) {
            vout = vv;
        } else {
#pragma unroll
            for (int j = 0; j < 8; j++)
                vsum2[j] = __hadd2(vsum2[j],
                                   *(const __half2*)&vsm_h[lane * 18 + 2 * j]);
        }
    }

    out[((size_t)b * N_P + t) * N_LOC + l] = vout;
}

// ---------------------------------------------------------------------------
extern "C" void kernel_launch(void* const* d_in, const int* in_sizes, int n_in,
                              void* d_out, int out_size) {
    const float* pose = (const float*)d_in[0];  // (4, 256, 14, 14)
    const float* W    = (const float*)d_in[1];  // (288, 512, 8)
    float* out = (float*)d_out;                 // (4, 512, 14, 14)

    cudaFuncSetAttribute(routing_kernel,
                         cudaFuncAttributeMaxDynamicSharedMemorySize, SM_TOTAL);

    pose_out_kernel<<<dim3(N_KKA, N_BL / TILE), 256>>>(pose, W);
    routing_kernel<<<N_BL, 512, SM_TOTAL>>>(out);
}

// round 16
// speedup vs baseline: 1.3874x; 1.3874x over previous
#include <cuda_runtime.h>
#include <cuda_fp16.h>

#define N_KKA 288
#define N_P   512
#define N_LOC 196
#define N_BL  784   // 4 * 196
#define TILE  56    // bl per kernel-A CTA (784 = 56*14)

#define CACHED_I 2           // i < 2 slices persist in smem for passes 1-2
#define SRED_ST  514         // h2 stride (16 warps * 32 + 2 pad)

typedef unsigned long long ull;

// 231 MB fp16 scratch, chunk-interleaved: half index =
//   bl*(288*512) + kka*512 + j*256 + bc*8 + dd   (d = j*8+dd, j=0..1)
__device__ __half2 g_po[(size_t)N_BL * N_KKA * 256];

__device__ __forceinline__ ull ffma2(ull a, ull b, ull c) {
    ull d;
    asm("fma.rn.f32x2 %0, %1, %2, %3;" : "=l"(d) : "l"(a), "l"(b), "l"(c));
    return d;
}
__device__ __forceinline__ ull pack2(float lo, float hi) {
    ull d;
    asm("mov.b64 %0, {%1, %2};" : "=l"(d) : "f"(lo), "f"(hi));
    return d;
}
__device__ __forceinline__ void unpack2(float& lo, float& hi, ull v) {
    asm("mov.b64 {%0, %1}, %2;" : "=f"(lo), "=f"(hi) : "l"(v));
}
__device__ __forceinline__ void cp_async16(unsigned saddr, const void* gptr) {
    asm volatile("cp.async.cg.shared.global [%0], [%1], 16;"
                 :: "r"(saddr), "l"(gptr) : "memory");
}
__device__ __forceinline__ void cp_commit() {
    asm volatile("cp.async.commit_group;" ::: "memory");
}

// ---------------------------------------------------------------------------
// Kernel A: EXACT round-12 version (proven 61us; near DRAM-write floor).
// ---------------------------------------------------------------------------
__global__ void __launch_bounds__(256) pose_out_kernel(
        const float* __restrict__ pose, const float* __restrict__ W) {
    const int kka  = blockIdx.x;
    const int tile = blockIdx.y;
    __shared__ float Wsm[N_P * 9];
    __shared__ float xsmT[8 * TILE];   // [c][blc]
    const int t = threadIdx.x;

    const float4* Wk4 = (const float4*)(W + (size_t)kka * (N_P * 8));
#pragma unroll
    for (int j = 0; j < 4; j++) {
        const int i4 = t + j * 256;
        const float4 w4 = Wk4[i4];
        const int p = i4 >> 1;
        const int cb = (i4 & 1) * 4;
        const int slot = ((p & 1) << 8) | ((p >> 4) << 3) | ((p & 15) >> 1);
        Wsm[slot * 9 + cb + 0] = w4.x;
        Wsm[slot * 9 + cb + 1] = w4.y;
        Wsm[slot * 9 + cb + 2] = w4.z;
        Wsm[slot * 9 + cb + 3] = w4.w;
    }

    const int a = kka & 31, kk = kka >> 5;
    const int ky = kk / 3, kx = kk % 3;
#pragma unroll
    for (int idx = t; idx < TILE * 8; idx += 256) {
        const int blc = idx >> 3, c = idx & 7;
        const int bl = tile * TILE + blc;
        const int b = bl / N_LOC, l = bl % N_LOC;
        const int oh = l / 14, ow = l % 14;
        const int ih = oh + ky - 1, iw = ow + kx - 1;
        float val = 0.f;
        if ((unsigned)ih < 14u && (unsigned)iw < 14u)
            val = pose[((b * 256 + a * 8 + c) * 14 + ih) * 14 + iw];
        xsmT[c * TILE + blc] = val;
    }
    __syncthreads();

    ull wd0[8], wd1[8];
#pragma unroll
    for (int c = 0; c < 8; c++) {
        const float a0 = Wsm[t * 9 + c];
        const float a1 = Wsm[(t + 256) * 9 + c];
        wd0[c] = pack2(a0, a0);
        wd1[c] = pack2(a1, a1);
    }
    const int slot_t = ((t & 4) << 5) | ((t >> 3) << 2) | (t & 3);
    __half2* dstbase = g_po + ((size_t)(tile * TILE) * N_KKA + kka) * 256 + slot_t;
#pragma unroll 2
    for (int pair = 0; pair < TILE / 2; pair++) {
        ull acc0 = 0ull, acc1 = 0ull;
#pragma unroll
        for (int c = 0; c < 8; c++) {
            const ull x2 = *(const ull*)&xsmT[c * TILE + pair * 2];
            acc0 = ffma2(wd0[c], x2, acc0);
            acc1 = ffma2(wd1[c], x2, acc1);
        }
        float a0A, a0B, a1A, a1B;
        unpack2(a0A, a0B, acc0);
        unpack2(a1A, a1B, acc1);
        __half2* dstA = dstbase + (size_t)(pair * 2) * (N_KKA * 256);
        __half2* dstB = dstA + (N_KKA * 256);
        *dstA = __floats2half2_rn(a0A, a1A);
        *dstB = __floats2half2_rn(a0B, a1B);
    }
}

// ---------------------------------------------------------------------------
// Kernel B helpers
// ---------------------------------------------------------------------------
__device__ __forceinline__ float softmax_c(float lg) {
    float es;
    {
        const float x = fmaf(lg, 1.44269504f, 16.0f);
        asm("ex2.approx.f32 %0, %1;" : "=f"(es) : "f"(x));
    }
    const unsigned ei = __float2uint_rn(es);
    unsigned si;
    asm("redux.sync.add.u32 %0, %1, 0xffffffff;" : "=r"(si) : "r"(ei));
    return __fdividef(es, __uint2float_rn(si));
}

// smem layout (bytes), 512-thread CTA (2 CTAs/SM) -- total = round-12 fit:
//   cache  : 0     .. 32768   (2 iterations * 16 kka * 1KB)
//   ring   : 32768 .. 81920   (3 slots * 16 kka * 1KB)
//   sred   : 81920 .. 98368
//   vsm    : 98368 .. 99520
#define SM_RING  32768
#define SM_SRED  81920
#define SM_VSM   98368
#define SM_TOTAL 99520

__device__ __forceinline__ float reduce_squash16(
        char* smem_raw, const __half2 s2[8], int t, int wid, int lane) {
    __half2* sred  = (__half2*)(smem_raw + SM_SRED);
    __half*  sredh = (__half*)(smem_raw + SM_SRED);
    __half*  vsm_h = (__half*)(smem_raw + SM_VSM);

#pragma unroll
    for (int j = 0; j < 8; j++)
        sred[j * SRED_ST + wid * 32 + lane] = s2[j];
    __syncthreads();

    const int bc = t >> 4, d = t & 15, j = d >> 1, par = d & 1;
    float stot = 0.f;
#pragma unroll
    for (int w = 0; w < 16; w++)
        stot += __half2float(sredh[2 * (j * SRED_ST + w * 32 + bc) + par]);

    float magsq = stot * stot;
#pragma unroll
    for (int off = 8; off; off >>= 1)
        magsq += __shfl_xor_sync(0xffffffffu, magsq, off);
    const float vv = stot * magsq / ((1.f + magsq) * sqrtf(magsq));
    vsm_h[bc * 18 + d] = __float2half_rn(vv);
    __syncthreads();
    return vv;
}

// ---------------------------------------------------------------------------
// Kernel B: 512 thr, 2 CTAs/SM, vsum trick. Pass 0 streams ALL 18 slices
// through cp.async: i=0,1 into the persistent cache, i=2..17 through a
// 3-slot per-thread ring (depth-3 groups, 6x16B outstanding/thread, no
// barriers: each thread consumes only addresses it wrote).
// ---------------------------------------------------------------------------
extern __shared__ char smem_raw[];

__global__ void __launch_bounds__(512, 2) routing_kernel(float* __restrict__ out) {
    float4* cache4 = (float4*)smem_raw;
    __half* vsm_h  = (__half*)(smem_raw + SM_VSM);

    const int bl = blockIdx.x;
    const int b = bl / N_LOC, l = bl % N_LOC;
    const int t = threadIdx.x;
    const int wid = t >> 5, lane = t & 31;

    const float4* po4 = (const float4*)(g_po + (size_t)bl * (N_KKA * 256));

    __half2 vsum2[8];
    float vout = 0.f;

    // ---------------- pass 0: c = 1/32, fully cp.async-streamed ----------------
    {
        __half2 s2[8];
#pragma unroll
        for (int j = 0; j < 8; j++) s2[j] = __float2half2_rn(0.f);
        const __half2 c2 = __float2half2_rn(0.03125f);

        const unsigned cbase = (unsigned)__cvta_generic_to_shared(smem_raw);

        // G0: cached i=0,1 + ring iteration 2 (slot 0)
#pragma unroll
        for (int i = 0; i < 2; i++) {
            const int kka = i * 16 + wid;
            const unsigned dst = cbase + (unsigned)((kka * 64 + lane) * 16);
            cp_async16(dst,       po4 + kka * 64 + lane);
            cp_async16(dst + 512, po4 + kka * 64 + 32 + lane);
        }
        {
            const int kka = 2 * 16 + wid;
            const unsigned dst = cbase + SM_RING + (unsigned)(((0 * 16 + wid) * 64 + lane) * 16);
            cp_async16(dst,       po4 + kka * 64 + lane);
            cp_async16(dst + 512, po4 + kka * 64 + 32 + lane);
        }
        cp_commit();
        // G1, G2: ring iterations 3, 4 (slots 1, 2)
#pragma unroll
        for (int s = 1; s < 3; s++) {
            const int kka = (2 + s) * 16 + wid;
            const unsigned dst = cbase + SM_RING + (unsigned)(((s * 16 + wid) * 64 + lane) * 16);
            cp_async16(dst,       po4 + kka * 64 + lane);
            cp_async16(dst + 512, po4 + kka * 64 + 32 + lane);
            cp_commit();
        }

        const float4* ring4 = (const float4*)(smem_raw + SM_RING);
#pragma unroll
        for (int i = 2; i < 18; i++) {
            asm volatile("cp.async.wait_group 2;" ::: "memory");
            const int s = (i - 2) % 3;
            const float4 q0 = ring4[(s * 16 + wid) * 64 + lane];
            const float4 q1 = ring4[(s * 16 + wid) * 64 + 32 + lane];
            const __half2* h0 = (const __half2*)&q0;
            const __half2* h1 = (const __half2*)&q1;
#pragma unroll
            for (int j = 0; j < 4; j++) {
                s2[j]     = __hfma2(c2, h0[j], s2[j]);
                s2[4 + j] = __hfma2(c2, h1[j], s2[4 + j]);
            }
            if (i + 3 < 18) {   // refill freed slot for iteration i+3
                const int kka = (i + 3) * 16 + wid;
                const unsigned dst = cbase + SM_RING + (unsigned)(((s * 16 + wid) * 64 + lane) * 16);
                cp_async16(dst,       po4 + kka * 64 + lane);
                cp_async16(dst + 512, po4 + kka * 64 + 32 + lane);
            }
            cp_commit();
        }

        // cached i=0,1 (completed with G0, guaranteed by the first wait above)
#pragma unroll
        for (int i = 0; i < CACHED_I; i++) {
            const int slot = (i * 16 + wid) * 64;
            const float4 c0 = cache4[slot + lane];
            const float4 c1 = cache4[slot + 32 + lane];
            const __half2* h0 = (const __half2*)&c0;
            const __half2* h1 = (const __half2*)&c1;
#pragma unroll
            for (int j = 0; j < 4; j++) {
                s2[j]     = __hfma2(c2, h0[j], s2[j]);
                s2[4 + j] = __hfma2(c2, h1[j], s2[4 + j]);
            }
        }

        reduce_squash16(smem_raw, s2, t, wid, lane);
#pragma unroll
        for (int j = 0; j < 8; j++)
            vsum2[j] = *(const __half2*)&vsm_h[lane * 18 + 2 * j];
    }

    // ---------------- passes 1 and 2 ----------------
#pragma unroll 1
    for (int pass = 1; pass < 3; pass++) {
        __half2 s2[8];
#pragma unroll
        for (int j = 0; j < 8; j++) s2[j] = __float2half2_rn(0.f);

        float4 q0 = cache4[wid * 64 + lane];
        float4 q1 = cache4[wid * 64 + 32 + lane];
#pragma unroll
        for (int i = 0; i < 18; i++) {
            float4 n0 = q0, n1 = q1;
            if (i < 17) {
                const int ii = i + 1;
                if (ii < CACHED_I) {
                    const int slot = (ii * 16 + wid) * 64;
                    n0 = cache4[slot + lane];
                    n1 = cache4[slot + 32 + lane];
                } else {
                    const int kka = ii * 16 + wid;
                    n0 = po4[kka * 64 + lane];
                    n1 = po4[kka * 64 + 32 + lane];
                }
            }
            __half2 r2[8];
            {
                const __half2* h0 = (const __half2*)&q0;
                const __half2* h1 = (const __half2*)&q1;
#pragma unroll
                for (int j = 0; j < 4; j++) { r2[j] = h0[j]; r2[4 + j] = h1[j]; }
            }
            __half2 acc0 = __hmul2(vsum2[0], r2[0]);
            acc0 = __hfma2(vsum2[1], r2[1], acc0);
            acc0 = __hfma2(vsum2[2], r2[2], acc0);
            acc0 = __hfma2(vsum2[3], r2[3], acc0);
            __half2 acc1 = __hmul2(vsum2[4], r2[4]);
            acc1 = __hfma2(vsum2[5], r2[5], acc1);
            acc1 = __hfma2(vsum2[6], r2[6], acc1);
            acc1 = __hfma2(vsum2[7], r2[7], acc1);
            const float2 df = __half22float2(__hadd2(acc0, acc1));
            const float lg = df.x + df.y;
            const __half2 c2 = __half2half2(__float2half_rn(softmax_c(lg)));
#pragma unroll
            for (int j = 0; j < 8; j++) s2[j] = __hfma2(c2, r2[j], s2[j]);
            q0 = n0; q1 = n1;
        }

        const float vv = reduce_squash16(smem_raw, s2, t, wid, lane);
        if (pass == 2) {
            vout = vv;
        } else {
#pragma unroll
            for (int j = 0; j < 8; j++)
                vsum2[j] = __hadd2(vsum2[j],
                                   *(const __half2*)&vsm_h[lane * 18 + 2 * j]);
        }
    }

    out[((size_t)b * N_P + t) * N_LOC + l] = vout;
}

// ---------------------------------------------------------------------------
extern "C" void kernel_launch(void* const* d_in, const int* in_sizes, int n_in,
                              void* d_out, int out_size) {
    const float* pose = (const float*)d_in[0];  // (4, 256, 14, 14)
    const float* W    = (const float*)d_in[1];  // (288, 512, 8)
    float* out = (float*)d_out;                 // (4, 512, 14, 14)

    cudaFuncSetAttribute(routing_kernel,
                         cudaFuncAttributeMaxDynamicSharedMemorySize, SM_TOTAL);

    pose_out_kernel<<<dim3(N_KKA, N_BL / TILE), 256>>>(pose, W);
    routing_kernel<<<N_BL, 512, SM_TOTAL>>>(out);
}

// round 17
// speedup vs baseline: 1.4051x; 1.0128x over previous
#include <cuda_runtime.h>
#include <cuda_fp16.h>

#define N_KKA 288
#define N_P   512
#define N_LOC 196
#define N_BL  784   // 4 * 196
#define TILE  56    // bl per kernel-A CTA (784 = 56*14)

#define CACHED_I 2           // i < 2 slices persist in smem for passes 1-2
#define SRED_ST  514         // h2 stride (16 warps * 32 + 2 pad)

typedef unsigned long long ull;

// 231 MB fp16 scratch, chunk-interleaved: half index =
//   bl*(288*512) + kka*512 + j*256 + bc*8 + dd   (d = j*8+dd, j=0..1)
__device__ __half2 g_po[(size_t)N_BL * N_KKA * 256];

__device__ __forceinline__ ull ffma2(ull a, ull b, ull c) {
    ull d;
    asm("fma.rn.f32x2 %0, %1, %2, %3;" : "=l"(d) : "l"(a), "l"(b), "l"(c));
    return d;
}
__device__ __forceinline__ ull pack2(float lo, float hi) {
    ull d;
    asm("mov.b64 %0, {%1, %2};" : "=l"(d) : "f"(lo), "f"(hi));
    return d;
}
__device__ __forceinline__ void unpack2(float& lo, float& hi, ull v) {
    asm("mov.b64 {%0, %1}, %2;" : "=f"(lo), "=f"(hi) : "l"(v));
}
__device__ __forceinline__ void cp_async16(unsigned saddr, const void* gptr) {
    asm volatile("cp.async.cg.shared.global [%0], [%1], 16;"
                 :: "r"(saddr), "l"(gptr) : "memory");
}
__device__ __forceinline__ void cp_commit() {
    asm volatile("cp.async.commit_group;" ::: "memory");
}

// ---------------------------------------------------------------------------
// Kernel A: round-12 version (proven ~61us; near DRAM-write floor).
// ---------------------------------------------------------------------------
__global__ void __launch_bounds__(256) pose_out_kernel(
        const float* __restrict__ pose, const float* __restrict__ W) {
    const int kka  = blockIdx.x;
    const int tile = blockIdx.y;
    __shared__ float Wsm[N_P * 9];
    __shared__ float xsmT[8 * TILE];   // [c][blc]
    const int t = threadIdx.x;

    const float4* Wk4 = (const float4*)(W + (size_t)kka * (N_P * 8));
#pragma unroll
    for (int j = 0; j < 4; j++) {
        const int i4 = t + j * 256;
        const float4 w4 = Wk4[i4];
        const int p = i4 >> 1;
        const int cb = (i4 & 1) * 4;
        const int slot = ((p & 1) << 8) | ((p >> 4) << 3) | ((p & 15) >> 1);
        Wsm[slot * 9 + cb + 0] = w4.x;
        Wsm[slot * 9 + cb + 1] = w4.y;
        Wsm[slot * 9 + cb + 2] = w4.z;
        Wsm[slot * 9 + cb + 3] = w4.w;
    }

    const int a = kka & 31, kk = kka >> 5;
    const int ky = kk / 3, kx = kk % 3;
#pragma unroll
    for (int idx = t; idx < TILE * 8; idx += 256) {
        const int blc = idx >> 3, c = idx & 7;
        const int bl = tile * TILE + blc;
        const int b = bl / N_LOC, l = bl % N_LOC;
        const int oh = l / 14, ow = l % 14;
        const int ih = oh + ky - 1, iw = ow + kx - 1;
        float val = 0.f;
        if ((unsigned)ih < 14u && (unsigned)iw < 14u)
            val = pose[((b * 256 + a * 8 + c) * 14 + ih) * 14 + iw];
        xsmT[c * TILE + blc] = val;
    }
    __syncthreads();

    ull wd0[8], wd1[8];
#pragma unroll
    for (int c = 0; c < 8; c++) {
        const float a0 = Wsm[t * 9 + c];
        const float a1 = Wsm[(t + 256) * 9 + c];
        wd0[c] = pack2(a0, a0);
        wd1[c] = pack2(a1, a1);
    }
    const int slot_t = ((t & 4) << 5) | ((t >> 3) << 2) | (t & 3);
    __half2* dstbase = g_po + ((size_t)(tile * TILE) * N_KKA + kka) * 256 + slot_t;
#pragma unroll 2
    for (int pair = 0; pair < TILE / 2; pair++) {
        ull acc0 = 0ull, acc1 = 0ull;
#pragma unroll
        for (int c = 0; c < 8; c++) {
            const ull x2 = *(const ull*)&xsmT[c * TILE + pair * 2];
            acc0 = ffma2(wd0[c], x2, acc0);
            acc1 = ffma2(wd1[c], x2, acc1);
        }
        float a0A, a0B, a1A, a1B;
        unpack2(a0A, a0B, acc0);
        unpack2(a1A, a1B, acc1);
        __half2* dstA = dstbase + (size_t)(pair * 2) * (N_KKA * 256);
        __half2* dstB = dstA + (N_KKA * 256);
        *dstA = __floats2half2_rn(a0A, a1A);
        *dstB = __floats2half2_rn(a0B, a1B);
    }
}

// ---------------------------------------------------------------------------
// Kernel B helpers
// ---------------------------------------------------------------------------
__device__ __forceinline__ float softmax_c(float lg) {
    float es;
    {
        const float x = fmaf(lg, 1.44269504f, 16.0f);
        asm("ex2.approx.f32 %0, %1;" : "=f"(es) : "f"(x));
    }
    const unsigned ei = __float2uint_rn(es);
    unsigned si;
    asm("redux.sync.add.u32 %0, %1, 0xffffffff;" : "=r"(si) : "r"(ei));
    return __fdividef(es, __uint2float_rn(si));
}

// smem layout (bytes), 512-thread CTA (2 CTAs/SM):
//   cache  : 0     .. 32768   (2 iterations * 16 kka * 1KB)
//   ring   : 32768 .. 81920   (3 slots * 16 kka * 1KB)
//   sred   : 81920 .. 98368
//   vsm    : 98368 .. 99520
#define SM_RING  32768
#define SM_SRED  81920
#define SM_VSM   98368
#define SM_TOTAL 99520

__device__ __forceinline__ float reduce_squash16(
        char* smem_raw, const __half2 s2[8], int t, int wid, int lane) {
    __half2* sred  = (__half2*)(smem_raw + SM_SRED);
    __half*  sredh = (__half*)(smem_raw + SM_SRED);
    __half*  vsm_h = (__half*)(smem_raw + SM_VSM);

#pragma unroll
    for (int j = 0; j < 8; j++)
        sred[j * SRED_ST + wid * 32 + lane] = s2[j];
    __syncthreads();

    const int bc = t >> 4, d = t & 15, j = d >> 1, par = d & 1;
    float stot = 0.f;
#pragma unroll
    for (int w = 0; w < 16; w++)
        stot += __half2float(sredh[2 * (j * SRED_ST + w * 32 + bc) + par]);

    float magsq = stot * stot;
#pragma unroll
    for (int off = 8; off; off >>= 1)
        magsq += __shfl_xor_sync(0xffffffffu, magsq, off);
    const float vv = stot * magsq / ((1.f + magsq) * sqrtf(magsq));
    vsm_h[bc * 18 + d] = __float2half_rn(vv);
    __syncthreads();
    return vv;
}

// prefill ring slots 0..2 with slices 2,3,4 (3 committed groups)
__device__ __forceinline__ void ring_prefill(
        unsigned cbase, const float4* po4, int wid, int lane) {
#pragma unroll
    for (int s = 0; s < 3; s++) {
        const int kka = (2 + s) * 16 + wid;
        const unsigned dst = cbase + SM_RING +
                             (unsigned)(((s * 16 + wid) * 64 + lane) * 16);
        cp_async16(dst,       po4 + kka * 64 + lane);
        cp_async16(dst + 512, po4 + kka * 64 + 32 + lane);
        cp_commit();
    }
}

// ---------------------------------------------------------------------------
// Kernel B: 512 thr, 2 CTAs/SM, vsum trick. ALL THREE passes stream i>=2
// through the per-thread 3-slot cp.async ring (depth-3 groups, barrier-free:
// each thread consumes only addresses it wrote). Each pass's first 3 ring
// groups are issued before the PREVIOUS pass's reduction, so the loads land
// during reduce_squash and the ring starts hot.
// ---------------------------------------------------------------------------
extern __shared__ char smem_raw[];

__global__ void __launch_bounds__(512, 2) routing_kernel(float* __restrict__ out) {
    float4* cache4 = (float4*)smem_raw;
    float4* ring4  = (float4*)(smem_raw + SM_RING);
    __half* vsm_h  = (__half*)(smem_raw + SM_VSM);

    const int bl = blockIdx.x;
    const int b = bl / N_LOC, l = bl % N_LOC;
    const int t = threadIdx.x;
    const int wid = t >> 5, lane = t & 31;

    const float4* po4 = (const float4*)(g_po + (size_t)bl * (N_KKA * 256));
    const unsigned cbase = (unsigned)__cvta_generic_to_shared(smem_raw);

    __half2 vsum2[8];
    float vout = 0.f;

    // ---------------- pass 0: c = 1/32, fully cp.async-streamed ----------------
    {
        __half2 s2[8];
#pragma unroll
        for (int j = 0; j < 8; j++) s2[j] = __float2half2_rn(0.f);
        const __half2 c2 = __float2half2_rn(0.03125f);

        // G0: cached i=0,1 + ring slice 2 (slot 0)
#pragma unroll
        for (int i = 0; i < 2; i++) {
            const int kka = i * 16 + wid;
            const unsigned dst = cbase + (unsigned)((kka * 64 + lane) * 16);
            cp_async16(dst,       po4 + kka * 64 + lane);
            cp_async16(dst + 512, po4 + kka * 64 + 32 + lane);
        }
        {
            const int kka = 2 * 16 + wid;
            const unsigned dst = cbase + SM_RING + (unsigned)(((0 * 16 + wid) * 64 + lane) * 16);
            cp_async16(dst,       po4 + kka * 64 + lane);
            cp_async16(dst + 512, po4 + kka * 64 + 32 + lane);
        }
        cp_commit();
        // G1, G2: ring slices 3, 4 (slots 1, 2)
#pragma unroll
        for (int s = 1; s < 3; s++) {
            const int kka = (2 + s) * 16 + wid;
            const unsigned dst = cbase + SM_RING + (unsigned)(((s * 16 + wid) * 64 + lane) * 16);
            cp_async16(dst,       po4 + kka * 64 + lane);
            cp_async16(dst + 512, po4 + kka * 64 + 32 + lane);
            cp_commit();
        }

#pragma unroll
        for (int i = 2; i < 18; i++) {
            asm volatile("cp.async.wait_group 2;" ::: "memory");
            const int s = (i - 2) % 3;
            const float4 q0 = ring4[(s * 16 + wid) * 64 + lane];
            const float4 q1 = ring4[(s * 16 + wid) * 64 + 32 + lane];
            const __half2* h0 = (const __half2*)&q0;
            const __half2* h1 = (const __half2*)&q1;
#pragma unroll
            for (int j = 0; j < 4; j++) {
                s2[j]     = __hfma2(c2, h0[j], s2[j]);
                s2[4 + j] = __hfma2(c2, h1[j], s2[4 + j]);
            }
            if (i + 3 < 18) {   // refill freed slot for slice i+3
                const int kka = (i + 3) * 16 + wid;
                const unsigned dst = cbase + SM_RING + (unsigned)(((s * 16 + wid) * 64 + lane) * 16);
                cp_async16(dst,       po4 + kka * 64 + lane);
                cp_async16(dst + 512, po4 + kka * 64 + 32 + lane);
            }
            cp_commit();
        }

        // cached i=0,1 (completed with G0)
#pragma unroll
        for (int i = 0; i < CACHED_I; i++) {
            const int slot = (i * 16 + wid) * 64;
            const float4 c0 = cache4[slot + lane];
            const float4 c1 = cache4[slot + 32 + lane];
            const __half2* h0 = (const __half2*)&c0;
            const __half2* h1 = (const __half2*)&c1;
#pragma unroll
            for (int j = 0; j < 4; j++) {
                s2[j]     = __hfma2(c2, h0[j], s2[j]);
                s2[4 + j] = __hfma2(c2, h1[j], s2[4 + j]);
            }
        }

        ring_prefill(cbase, po4, wid, lane);   // pass-1 warm-up overlaps reduce
        reduce_squash16(smem_raw, s2, t, wid, lane);
#pragma unroll
        for (int j = 0; j < 8; j++)
            vsum2[j] = *(const __half2*)&vsm_h[lane * 18 + 2 * j];
    }

    // ---------------- passes 1 and 2: logit = vsum . r, ring-streamed ----------------
#pragma unroll 1
    for (int pass = 1; pass < 3; pass++) {
        __half2 s2[8];
#pragma unroll
        for (int j = 0; j < 8; j++) s2[j] = __float2half2_rn(0.f);

#pragma unroll
        for (int i = 0; i < 18; i++) {
            float4 q0, q1;
            if (i < CACHED_I) {
                const int slot = (i * 16 + wid) * 64;
                q0 = cache4[slot + lane];
                q1 = cache4[slot + 32 + lane];
            } else {
                asm volatile("cp.async.wait_group 2;" ::: "memory");
                const int s = (i - 2) % 3;
                q0 = ring4[(s * 16 + wid) * 64 + lane];
                q1 = ring4[(s * 16 + wid) * 64 + 32 + lane];
            }
            __half2 r2[8];
            {
                const __half2* h0 = (const __half2*)&q0;
                const __half2* h1 = (const __half2*)&q1;
#pragma unroll
                for (int j = 0; j < 4; j++) { r2[j] = h0[j]; r2[4 + j] = h1[j]; }
            }
            __half2 acc0 = __hmul2(vsum2[0], r2[0]);
            acc0 = __hfma2(vsum2[1], r2[1], acc0);
            acc0 = __hfma2(vsum2[2], r2[2], acc0);
            acc0 = __hfma2(vsum2[3], r2[3], acc0);
            __half2 acc1 = __hmul2(vsum2[4], r2[4]);
            acc1 = __hfma2(vsum2[5], r2[5], acc1);
            acc1 = __hfma2(vsum2[6], r2[6], acc1);
            acc1 = __hfma2(vsum2[7], r2[7], acc1);
            const float2 df = __half22float2(__hadd2(acc0, acc1));
            const float lg = df.x + df.y;
            const __half2 c2 = __half2half2(__float2half_rn(softmax_c(lg)));
#pragma unroll
            for (int j = 0; j < 8; j++) s2[j] = __hfma2(c2, r2[j], s2[j]);

            if (i >= 2) {
                if (i + 3 < 18) {
                    const int s = (i - 2) % 3;
                    const int kka = (i + 3) * 16 + wid;
                    const unsigned dst = cbase + SM_RING + (unsigned)(((s * 16 + wid) * 64 + lane) * 16);
                    cp_async16(dst,       po4 + kka * 64 + lane);
                    cp_async16(dst + 512, po4 + kka * 64 + 32 + lane);
                }
                cp_commit();
            }
        }

        if (pass == 1)
            ring_prefill(cbase, po4, wid, lane);   // pass-2 warm-up

        const float vv = reduce_squash16(smem_raw, s2, t, wid, lane);
        if (pass == 2) {
            vout = vv;
        } else {
#pragma unroll
            for (int j = 0; j < 8; j++)
                vsum2[j] = __hadd2(vsum2[j],
                                   *(const __half2*)&vsm_h[lane * 18 + 2 * j]);
        }
    }

    out[((size_t)b * N_P + t) * N_LOC + l] = vout;
}

// ---------------------------------------------------------------------------
extern "C" void kernel_launch(void* const* d_in, const int* in_sizes, int n_in,
                              void* d_out, int out_size) {
    const float* pose = (const float*)d_in[0];  // (4, 256, 14, 14)
    const float* W    = (const float*)d_in[1];  // (288, 512, 8)
    float* out = (float*)d_out;                 // (4, 512, 14, 14)

    cudaFuncSetAttribute(routing_kernel,
                         cudaFuncAttributeMaxDynamicSharedMemorySize, SM_TOTAL);

    pose_out_kernel<<<dim3(N_KKA, N_BL / TILE), 256>>>(pose, W);
    routing_kernel<<<N_BL, 512, SM_TOTAL>>>(out);
}